// round 13
// baseline (speedup 1.0000x reference)
#include <cuda_runtime.h>

// Problem constants (fixed by setup_inputs): B=64, T=8000, M=80
#define B_   64
#define T_   8000
#define M_   80
#define MP   (M_ / 2)            // 40 mel-pairs; each thread owns 2 adjacent mels
#define TC   80                  // timesteps per block-chunk (contiguous 25.6KB)
#define SUBS 8                   // time-subchunks per chunk
#define TSUB (TC / SUBS)         // 10 timesteps per thread
#define NC   (T_ / TC)           // 100 chunks
#define THREADS 320              // 40 mel-pairs x 8 subchunks (warp count unchanged vs R12)
#define EPS 1e-6f
#define SENTINEL 0xFFFFFFFFu     // -NaN bits; published values are finite -> no collision
#define CSTRIDE (B_ * MP)        // slot stride between consecutive chunks
#define LBATCH 4                 // lookback walk MLP batch
#define CHUNK_FLOATS (TC * M_)   // 6400
#define CHUNK_VEC4   (CHUNK_FLOATS / 4)

// Per-(chunk,b,mel-pair) slots: {lane0,lane1} floats packed in 64 bits.
__device__ unsigned long long g_loc[NC * B_ * MP];   // local chunk endpoints
__device__ unsigned long long g_inc[NC * B_ * MP];   // inclusive endpoints
__device__ float4 g_pow[M_];   // (-alpha, r, delta, delta^r)
__device__ float4 g_ema[M_];   // (s, 1-s, (1-s)^TSUB, (1-s)^TC)

__device__ __forceinline__ float fast_log2(float x) {
    float y; asm("lg2.approx.f32 %0, %1;" : "=f"(y) : "f"(x)); return y;
}
__device__ __forceinline__ float fast_exp2(float x) {
    float y; asm("ex2.approx.f32 %0, %1;" : "=f"(y) : "f"(x)); return y;
}
__device__ __forceinline__ unsigned long long ld_relaxed64(const unsigned long long* p) {
    unsigned long long v;
    asm volatile("ld.relaxed.gpu.b64 %0, [%1];" : "=l"(v) : "l"(p) : "memory");
    return v;
}
__device__ __forceinline__ void st_release64(unsigned long long* p, unsigned long long v) {
    asm volatile("st.release.gpu.b64 [%0], %1;" :: "l"(p), "l"(v) : "memory");
}
__device__ __forceinline__ void st_stream2(float* p, float a, float b) {
    asm volatile("st.global.cs.v2.f32 [%0], {%1, %2};" :: "l"(p), "f"(a), "f"(b) : "memory");
}
__device__ __forceinline__ unsigned long long pack2(float a, float b) {
    return (unsigned long long)__float_as_uint(a) |
           ((unsigned long long)__float_as_uint(b) << 32);
}
__device__ __forceinline__ float lo_f(unsigned long long v) { return __uint_as_float((unsigned)v); }
__device__ __forceinline__ float hi_f(unsigned long long v) { return __uint_as_float((unsigned)(v >> 32)); }

// Init: sentinel-fill slots + per-mel params (block 0).
__global__ void pcen_init_kernel(const float* __restrict__ log_s,
                                 const float* __restrict__ log_alpha,
                                 const float* __restrict__ log_delta,
                                 const float* __restrict__ log_r)
{
    const int i = blockIdx.x * blockDim.x + threadIdx.x;
    if (i < NC * B_ * MP) { g_loc[i] = ~0ULL; g_inc[i] = ~0ULL; }
    if (blockIdx.x == 0 && threadIdx.x < M_) {
        const int m = threadIdx.x;
        const float s     = expf(log_s[m]);
        const float om    = 1.0f - s;
        const float alpha = expf(log_alpha[m]);
        const float delta = expf(log_delta[m]);
        const float r     = expf(log_r[m]);
        g_pow[m] = make_float4(-alpha, r, delta, powf(delta, r));
        g_ema[m] = make_float4(s, om, powf(om, (float)TSUB), powf(om, (float)TC));
    }
}

extern __shared__ float smem[];
// layout: s_x[6400] | s_l[SUBS*MP] float2 (sub-scan endpoints) | s_c[MP] float2 (carries)

__global__ __launch_bounds__(THREADS)
void pcen_block_kernel(const float* __restrict__ x, float* __restrict__ out)
{
    float*  const s_x = smem;
    float2* const s_l = (float2*)(smem + CHUNK_FLOATS);
    float2* const s_c = s_l + SUBS * MP;

    const int tid = threadIdx.x;
    const int bid = blockIdx.x;
    const int b   = bid % B_;
    const int c   = bid / B_;          // chunk-major: predecessors scheduled first
    const int mp  = tid % MP;
    const int sub = tid / MP;          // 0..7
    const int base = (b * T_ + c * TC) * M_;   // contiguous 6400-float chunk
    const int sidx = c * CSTRIDE + b * MP + mp;

    const int m0 = 2 * mp;
    const float4 E0 = g_ema[m0], E1 = g_ema[m0 + 1];
    const float4 P0 = g_pow[m0], P1 = g_pow[m0 + 1];
    const float s0 = E0.x, om0 = E0.y, omts0 = E0.z, pTc0 = E0.w;
    const float s1 = E1.x, om1 = E1.y, omts1 = E1.z, pTc1 = E1.w;

    // ---- stage the whole chunk DRAM->SMEM with 16B cp.async (max MLP, 0 regs) ----
    {
        const float4* src = (const float4*)(x + base);
        const unsigned sb = (unsigned)__cvta_generic_to_shared(s_x);
        #pragma unroll
        for (int i = 0; i < CHUNK_VEC4 / THREADS; ++i) {
            const int idx = tid + i * THREADS;
            asm volatile("cp.async.ca.shared.global [%0], [%1], 16;"
                         :: "r"(sb + 16u * idx), "l"(src + idx) : "memory");
        }
        asm volatile("cp.async.commit_group;" ::: "memory");
    }

    // ---- probe-only prefetch of predecessor inclusive: NO SPIN before our publish ----
    unsigned long long v0 = ~0ULL;
    if (sub == 0 && c > 0) v0 = ld_relaxed64(&g_inc[sidx - CSTRIDE]);

    asm volatile("cp.async.wait_group 0;" ::: "memory");
    __syncthreads();

    // ---- sub-scan: 10 timesteps x 2 mels per thread (LDS.64), s factored out ----
    float l0 = 0.f, l1 = 0.f;
    const int t0 = sub * TSUB;
    {
        const float2* px = (const float2*)(s_x + t0 * M_ + m0);
        #pragma unroll
        for (int k = 0; k < TSUB; ++k) {
            const float2 xv = px[k * MP];
            l0 = fmaf(om0, l0, xv.x);
            l1 = fmaf(om1, l1, xv.y);
        }
    }
    s_l[sub * MP + mp] = make_float2(l0 * s0, l1 * s1);
    __syncthreads();

    // ---- sub==0 (tid<40): combine subs, publish local, resolve carry, publish inclusive ----
    if (sub == 0) {
        float lend0 = 0.f, lend1 = 0.f;
        #pragma unroll
        for (int j = 0; j < SUBS; ++j) {
            const float2 L = s_l[j * MP + mp];
            lend0 = fmaf(omts0, lend0, L.x);
            lend1 = fmaf(omts1, lend1, L.y);
        }
        // publish local BEFORE any spin: successors can always make progress
        st_release64(&g_loc[sidx], pack2(lend0, lend1));

        float c0 = 0.f, c1 = 0.f;
        if (c > 0) {
            if ((unsigned)v0 != SENTINEL) {
                c0 = lo_f(v0); c1 = hi_f(v0);            // prefetch hit: free carry
            } else {
                float a0 = 0.f, a1 = 0.f, w0 = 1.f, w1 = 1.f;
                for (int j = c - 1; ; --j) {
                    unsigned long long iv = ld_relaxed64(&g_inc[j * CSTRIDE + b * MP + mp]);
                    if ((unsigned)iv != SENTINEL) {      // inclusive found -> terminate
                        c0 = fmaf(w0, lo_f(iv), a0);
                        c1 = fmaf(w1, hi_f(iv), a1);
                        break;
                    }
                    unsigned long long lv = ld_relaxed64(&g_loc[j * CSTRIDE + b * MP + mp]);
                    while ((unsigned)lv == SENTINEL) {   // poll BOTH slots (no deadlock)
                        __nanosleep(32);
                        iv = ld_relaxed64(&g_inc[j * CSTRIDE + b * MP + mp]);
                        if ((unsigned)iv != SENTINEL) break;
                        lv = ld_relaxed64(&g_loc[j * CSTRIDE + b * MP + mp]);
                    }
                    if ((unsigned)iv != SENTINEL) {
                        c0 = fmaf(w0, lo_f(iv), a0);
                        c1 = fmaf(w1, hi_f(iv), a1);
                        break;
                    }
                    a0 = fmaf(w0, lo_f(lv), a0);
                    a1 = fmaf(w1, hi_f(lv), a1);
                    w0 *= pTc0; w1 *= pTc1;
                    if (j == 0) { c0 = a0; c1 = a1; break; }
                }
            }
        }
        st_release64(&g_inc[sidx], pack2(fmaf(pTc0, c0, lend0), fmaf(pTc1, c1, lend1)));
        s_c[mp] = make_float2(c0, c1);
    }
    __syncthreads();

    // ---- start state for this sub: start = omts*start_prev + L_prev ----
    const float2 cv = s_c[mp];
    float mr0 = cv.x, mr1 = cv.y;
    #pragma unroll
    for (int j = 0; j < SUBS - 1; ++j)
        if (j < sub) {
            const float2 L = s_l[j * MP + mp];
            mr0 = fmaf(omts0, mr0, L.x);
            mr1 = fmaf(omts1, mr1, L.y);
        }

    // ---- rescan + compress + stream out: LDS.64 in, 2 MUFU chains, STG.64 out ----
    {
        const float2* px = (const float2*)(s_x + t0 * M_ + m0);
        float*        po = out + base + t0 * M_ + m0;
        #pragma unroll 5
        for (int k = 0; k < TSUB; ++k) {
            const float2 xv = px[k * MP];
            mr0 = fmaf(om0, mr0, s0 * xv.x);
            mr1 = fmaf(om1, mr1, s1 * xv.y);
            const float v0f = xv.x * fast_exp2(P0.x * fast_log2(mr0 + EPS));
            const float v1f = xv.y * fast_exp2(P1.x * fast_log2(mr1 + EPS));
            const float o0 = fast_exp2(P0.y * fast_log2(v0f + P0.z)) - P0.w;
            const float o1 = fast_exp2(P1.y * fast_log2(v1f + P1.z)) - P1.w;
            st_stream2(po + k * M_, o0, o1);             // evict-first 8B store
        }
    }
}

extern "C" void kernel_launch(void* const* d_in, const int* in_sizes, int n_in,
                              void* d_out, int out_size)
{
    const float* x  = (const float*)d_in[0];
    const float* ls = (const float*)d_in[1];
    const float* la = (const float*)d_in[2];
    const float* ld = (const float*)d_in[3];
    const float* lr = (const float*)d_in[4];
    float* out = (float*)d_out;

    const int smem_bytes = CHUNK_FLOATS * (int)sizeof(float)
                         + (SUBS * MP + MP) * (int)sizeof(float2);   // ~28.5 KB
    cudaFuncSetAttribute(pcen_block_kernel,
                         cudaFuncAttributeMaxDynamicSharedMemorySize, smem_bytes);

    pcen_init_kernel<<<(NC * B_ * MP + 255) / 256, 256>>>(ls, la, ld, lr);
    pcen_block_kernel<<<NC * B_, THREADS, smem_bytes>>>(x, out);
}